// round 15
// baseline (speedup 1.0000x reference)
#include <cuda_runtime.h>
#include <stdint.h>

// SRP map on GB300 — round 11.
//
// maps[f,g] = sum_{k!=l} x[f, k*12+l, tau0[k,l,g]], then per-frame
// zero-mean + /max. Wrapped lags in {0..7} U {504..511} -> 16 slots.
//
// R11 vs R13-best (17.2us; gather 13.2us at issue 40%, L1 35%):
//  * tcgen05 is NOT available in this bench env (ptxas targets sm_103
//    without the 'a' feature) — R10's GEMM route is dead. Back to gather.
//  * 4 FRAMES PER CTA: xsm holds float4 (f0..f3) per folded entry;
//    inner body LDS.32 tau + 4x(PRMT+IADD+LDS.128+2xFADD2) = 21 inst per
//    16 frame-values (1.3 inst/value vs 2.1 before). Same crossbar bytes.
//  * tau bytes now slot*16 (LDS.128 offset). One tau word + one staging
//    pass serve 4 frames.
//  * Kept (all verified): pair folding (exact antisymmetry), diagonal drop,
//    hoisted fold table, cp.async staging, coalesced tau layout,
//    fused last-CTA normalization with self-resetting counter.

#define KLEN    512
#define GPTS    2048
#define THREADS 128
#define NFOLD   66
#define NROWS   68
#define NENT    (NROWS * 16)        // 1088 entries
#define NCHUNK  17
#define NSPLIT  16
#define NF4     64                  // frame quads (256 frames / 4)
#define PACK_BLOCKS (NCHUNK * 32)   // 544
#define FOLD_SPLIT 4

__constant__ uint8_t c_pairA[NFOLD] = {
  1,2,3,4,5,6,7,8,9,10,11,
  14,15,16,17,18,19,20,21,22,23,
  27,28,29,30,31,32,33,34,35,
  40,41,42,43,44,45,46,47,
  53,54,55,56,57,58,59,
  66,67,68,69,70,71,
  79,80,81,82,83,
  92,93,94,95,
  105,106,107,
  118,119,
  131};
__constant__ uint8_t c_pairB[NFOLD] = {
  12,24,36,48,60,72,84,96,108,120,132,
  25,37,49,61,73,85,97,109,121,133,
  38,50,62,74,86,98,110,122,134,
  51,63,75,87,99,111,123,135,
  64,76,88,100,112,124,136,
  77,89,101,113,125,137,
  90,102,114,126,138,
  103,115,127,139,
  116,128,140,
  129,141,
  142};

// g_tauB[c*2048+g]: 4 bytes = slot*16 (LDS.128 offset) for pairs 4c..4c+3.
__device__ __align__(16) uint32_t g_tauB[NCHUNK * GPTS];
// folded x table: y4[f4][entry] = (y_f0, y_f1, y_f2, y_f3)
__device__ __align__(16) float4 g_y4[NF4 * NENT];          // 4.5 MB
// last-arrival workspace
__device__ float ws_s[256 * NSPLIT];
__device__ float ws_m[256 * NSPLIT];
__device__ int   ws_c[NF4];              // zero-init; self-resetting

__device__ __forceinline__ int lag_of(int s) { return (s < 8) ? s : (s + 496); }

__device__ __forceinline__ uint32_t smem_u32(const void* p) {
    return (uint32_t)__cvta_generic_to_shared(p);
}
__device__ __forceinline__ void cp16(uint32_t dst, const void* src) {
    asm volatile("cp.async.cg.shared.global [%0], [%1], 16;\n"
                 :: "r"(dst), "l"(src) : "memory");
}

// ---- prep: tau pack (blocks 0..543) + fold (4 blocks per frame quad) ----
__global__ void __launch_bounds__(256) prep_kernel(
    const int* __restrict__ tau0, const float* __restrict__ x)
{
    __shared__ uint8_t sm[256];
    const int tid = threadIdx.x;

    if (blockIdx.x < PACK_BLOCKS) {
        const int c  = blockIdx.x >> 5;
        const int gb = blockIdx.x & 31;
        const int j  = tid >> 6;
        const int gl = tid & 63;
        const int pr = c * 4 + j;
        uint8_t b = 0;
        if (pr < NFOLD) {
            uint32_t t = (uint32_t)__ldg(&tau0[(int)c_pairA[pr] * GPTS + gb * 64 + gl]);
            b = (uint8_t)((t & 15u) << 4);       // slot*16
        }
        sm[gl * 4 + j] = b;
        __syncthreads();
        if (tid < 64)
            g_tauB[c * GPTS + gb * 64 + tid] = ((const uint32_t*)sm)[tid];
    } else {
        const int q  = blockIdx.x - PACK_BLOCKS;
        const int f4 = q >> 2;                   // frame quad
        const int qt = q & 3;                    // quarter: 272 entries
        float4* dst = g_y4 + f4 * NENT;
        const int base = qt * 272;
#pragma unroll 2
        for (int e0 = 0; e0 < 2; e0++) {
            int e = base + e0 * 256 + tid;
            if (e0 == 1 && tid >= 16) break;
            int i = e - base;
            if (i >= 272) continue;
            int r = e >> 4, sl = e & 15;
            float4 v = make_float4(0.f, 0.f, 0.f, 0.f);
            if (r < NFOLD) {
                int ra = (int)c_pairA[r] * KLEN + lag_of(sl);
                int rb = (int)c_pairB[r] * KLEN + lag_of((16 - sl) & 15);
                const float* x0 = x + (size_t)(f4 * 4 + 0) * (144 * KLEN);
                const float* x1 = x + (size_t)(f4 * 4 + 1) * (144 * KLEN);
                const float* x2 = x + (size_t)(f4 * 4 + 2) * (144 * KLEN);
                const float* x3 = x + (size_t)(f4 * 4 + 3) * (144 * KLEN);
                v.x = __ldg(&x0[ra]) + __ldg(&x0[rb]);
                v.y = __ldg(&x1[ra]) + __ldg(&x1[rb]);
                v.z = __ldg(&x2[ra]) + __ldg(&x2[rb]);
                v.w = __ldg(&x3[ra]) + __ldg(&x3[rb]);
            }
            dst[e] = v;
        }
    }
}

// ---------------- gather + fused normalization ----------------
// CTA: f4 = blockIdx.x>>4 (frame quad), s = blockIdx.x&15.  128 threads,
// each owns point g = s*128 + tid for 4 frames.
__global__ void __launch_bounds__(THREADS) srp_gather_kernel(
    const float* __restrict__ x, float* __restrict__ out)
{
    __shared__ __align__(16) float4   xsm[NENT];              // 17408 B
    __shared__ __align__(16) uint32_t stau[NCHUNK * THREADS]; // 8704 B
    __shared__ float red[8][THREADS / 32];
    __shared__ float bcast[8];
    __shared__ int   is_last;

    const int f4  = blockIdx.x >> 4;
    const int s   = blockIdx.x & 15;
    const int tid = threadIdx.x;

    // ---- Async-stage tau slice: stau[c*128+j] = g_tauB[c*2048 + s*128 + j] ----
    {
        const char* src_base = (const char*)g_tauB + (size_t)s * 512;
        uint32_t dst_base = smem_u32(stau);
#pragma unroll
        for (int k = 0; k < 5; k++) {
            int o = tid + k * THREADS;            // 16B-op index, 544 total
            if (o < NCHUNK * 32) {
                int c   = o >> 5;
                int off = (o & 31) * 16;
                cp16(dst_base + c * 512 + off, src_base + (size_t)c * 8192 + off);
            }
        }
    }
    // ---- Async-stage folded y4 table (1088 x 16B) ----
    {
        const char* src = (const char*)(g_y4 + f4 * NENT);
        uint32_t dst = smem_u32(xsm);
#pragma unroll
        for (int k = 0; k < 9; k++) {
            int o = tid + k * THREADS;
            if (o < NENT) cp16(dst + o * 16, src + o * 16);
        }
    }
    asm volatile("cp.async.commit_group;\n" ::: "memory");
    asm volatile("cp.async.wait_group 0;\n" ::: "memory");
    __syncthreads();

    const int g = s * THREADS + tid;
    const char* xbase = (const char*)xsm;

    // 8 packed accumulators: accJ = (pairsum for frames 2J, 2J+1) per lane j
    unsigned long long ac[4][2];
#pragma unroll
    for (int j = 0; j < 4; j++) { ac[j][0] = 0ull; ac[j][1] = 0ull; }

#pragma unroll
    for (int c = 0; c < NCHUNK; c++) {
        uint32_t w = stau[c * THREADS + tid];     // LDS.32, conflict-free
        const char* cb = xbase + c * 1024;
        uint4 q0 = *(const uint4*)(cb +   0 + __byte_perm(w, 0, 0x4440));
        uint4 q1 = *(const uint4*)(cb + 256 + __byte_perm(w, 0, 0x4441));
        uint4 q2 = *(const uint4*)(cb + 512 + __byte_perm(w, 0, 0x4442));
        uint4 q3 = *(const uint4*)(cb + 768 + __byte_perm(w, 0, 0x4443));
        unsigned long long lo, hi;
        asm("mov.b64 %0, {%2, %3}; mov.b64 %1, {%4, %5};"
            : "=l"(lo), "=l"(hi) : "r"(q0.x), "r"(q0.y), "r"(q0.z), "r"(q0.w));
        asm("add.rn.f32x2 %0, %0, %1;" : "+l"(ac[0][0]) : "l"(lo));
        asm("add.rn.f32x2 %0, %0, %1;" : "+l"(ac[0][1]) : "l"(hi));
        asm("mov.b64 %0, {%2, %3}; mov.b64 %1, {%4, %5};"
            : "=l"(lo), "=l"(hi) : "r"(q1.x), "r"(q1.y), "r"(q1.z), "r"(q1.w));
        asm("add.rn.f32x2 %0, %0, %1;" : "+l"(ac[1][0]) : "l"(lo));
        asm("add.rn.f32x2 %0, %0, %1;" : "+l"(ac[1][1]) : "l"(hi));
        asm("mov.b64 %0, {%2, %3}; mov.b64 %1, {%4, %5};"
            : "=l"(lo), "=l"(hi) : "r"(q2.x), "r"(q2.y), "r"(q2.z), "r"(q2.w));
        asm("add.rn.f32x2 %0, %0, %1;" : "+l"(ac[2][0]) : "l"(lo));
        asm("add.rn.f32x2 %0, %0, %1;" : "+l"(ac[2][1]) : "l"(hi));
        asm("mov.b64 %0, {%2, %3}; mov.b64 %1, {%4, %5};"
            : "=l"(lo), "=l"(hi) : "r"(q3.x), "r"(q3.y), "r"(q3.z), "r"(q3.w));
        asm("add.rn.f32x2 %0, %0, %1;" : "+l"(ac[3][0]) : "l"(lo));
        asm("add.rn.f32x2 %0, %0, %1;" : "+l"(ac[3][1]) : "l"(hi));
    }

    // reduce 4 pair-lanes -> per-frame values v[0..3]
    float v[4];
    {
        float2 p01_a = *(float2*)&ac[0][0], p01_b = *(float2*)&ac[1][0];
        float2 p01_c = *(float2*)&ac[2][0], p01_d = *(float2*)&ac[3][0];
        float2 p23_a = *(float2*)&ac[0][1], p23_b = *(float2*)&ac[1][1];
        float2 p23_c = *(float2*)&ac[2][1], p23_d = *(float2*)&ac[3][1];
        v[0] = (p01_a.x + p01_b.x) + (p01_c.x + p01_d.x);
        v[1] = (p01_a.y + p01_b.y) + (p01_c.y + p01_d.y);
        v[2] = (p23_a.x + p23_b.x) + (p23_c.x + p23_d.x);
        v[3] = (p23_a.y + p23_b.y) + (p23_c.y + p23_d.y);
    }

#pragma unroll
    for (int fr = 0; fr < 4; fr++)
        out[(size_t)(f4 * 4 + fr) * GPTS + g] = v[fr];

    // ---- CTA-local partial sum/max per frame ----
    float ps[4], pm[4];
#pragma unroll
    for (int fr = 0; fr < 4; fr++) { ps[fr] = v[fr]; pm[fr] = v[fr]; }
#pragma unroll
    for (int o = 16; o > 0; o >>= 1) {
#pragma unroll
        for (int fr = 0; fr < 4; fr++) {
            ps[fr] += __shfl_xor_sync(0xFFFFFFFFu, ps[fr], o);
            pm[fr] = fmaxf(pm[fr], __shfl_xor_sync(0xFFFFFFFFu, pm[fr], o));
        }
    }
    int wid = tid >> 5, lane = tid & 31;
    if (lane == 0) {
#pragma unroll
        for (int fr = 0; fr < 4; fr++) {
            red[fr * 2][wid]     = ps[fr];
            red[fr * 2 + 1][wid] = pm[fr];
        }
    }
    __syncthreads();

    if (tid == 0) {
#pragma unroll
        for (int fr = 0; fr < 4; fr++) {
            float cs = 0.f, cm = -3.0e38f;
#pragma unroll
            for (int wq = 0; wq < THREADS / 32; wq++) {
                cs += red[fr * 2][wq];
                cm = fmaxf(cm, red[fr * 2 + 1][wq]);
            }
            ws_s[(f4 * 4 + fr) * NSPLIT + s] = cs;
            ws_m[(f4 * 4 + fr) * NSPLIT + s] = cm;
        }
        __threadfence();
        int old = atomicAdd(&ws_c[f4], 1);
        is_last = (old == NSPLIT - 1) ? 1 : 0;
    }
    __syncthreads();
    if (!is_last) return;

    // ---- Last CTA of this frame quad: normalize 4 frames ----
    if (tid == 0) {
        __threadfence();
        ws_c[f4] = 0;                            // reset for next graph replay
        const float EPS = 1e-12f;
#pragma unroll
        for (int fr = 0; fr < 4; fr++) {
            int f = f4 * 4 + fr;
            float tot = 0.f, mm = -3.0e38f;
#pragma unroll
            for (int k = 0; k < NSPLIT; k++) {   // fixed order: deterministic
                tot += ws_s[f * NSPLIT + k];
                mm = fmaxf(mm, ws_m[f * NSPLIT + k]);
            }
            float mean = tot * (1.0f / (float)GPTS);
            bcast[fr * 2]     = mean;
            bcast[fr * 2 + 1] = 1.0f / (mm - mean + EPS);
        }
    }
    __syncthreads();

    const float EPS = 1e-12f;
#pragma unroll
    for (int fr = 0; fr < 4; fr++) {
        float* of  = out + (size_t)(f4 * 4 + fr) * GPTS;
        float mean = bcast[fr * 2];
        float inv  = bcast[fr * 2 + 1];
#pragma unroll
        for (int e = 0; e < 4; e++) {
            float4 q = *(const float4*)(of + e * 512 + tid * 4);
            q.x = (q.x - mean + EPS) * inv;
            q.y = (q.y - mean + EPS) * inv;
            q.z = (q.z - mean + EPS) * inv;
            q.w = (q.w - mean + EPS) * inv;
            *(float4*)(of + e * 512 + tid * 4) = q;
        }
    }
}

extern "C" void kernel_launch(void* const* d_in, const int* in_sizes, int n_in,
                              void* d_out, int out_size)
{
    const float* x;
    const int*   tau0;
    if (in_sizes[0] == 144 * GPTS) {
        tau0 = (const int*)d_in[0];
        x    = (const float*)d_in[1];
    } else {
        x    = (const float*)d_in[0];
        tau0 = (const int*)d_in[1];
    }

    int nframes = out_size / GPTS;      // 256
    int nf4     = nframes / 4;          // 64 frame quads

    prep_kernel<<<PACK_BLOCKS + nf4 * FOLD_SPLIT, 256>>>(tau0, x);
    srp_gather_kernel<<<nf4 * NSPLIT, THREADS>>>(x, (float*)d_out);
}